// round 5
// baseline (speedup 1.0000x reference)
#include <cuda_runtime.h>
#include <cuda_bf16.h>
#include <stdint.h>

#define NB 2
#define NH 48
#define NW 48
#define ND 24
#define NA 9
#define NK 20
#define TOTAL  497664            // NH*NW*ND*NA
#define HWD    55296             // NH*NW*ND
#define OUTTOT 995328            // NB*NA*HWD
#define NUMFG 128
#define RPNB  256
#define NBINS 65536
#define BPB   243                // blocks per batch in pass A/B (2048 anchors each)
#define CAP   4096               // per-group candidate buffer (threshold bin members)

#define OFF_BT  995328
#define OFF_IW  (OFF_BT + 5971968)
#define OFF_OW  (OFF_IW + 5971968)

// ---------------- device scratch (no allocations allowed) ----------------
__device__ float              g_gt[NB * NK * 7];    // x1 y1 x2 y2 z1 z2 area (mangled for zero-size)
__device__ float              g_gtd[NB * NK * 6];   // gcx gcy gcz log(gw) log(gh) log(gd)
__device__ float              g_ancd[NA * 9];       // cxa cya cza 1/ew 1/eh 1/ed lew leh led
__device__ int                g_gtmax[NB * NK];     // float-as-int max IoU per gt
__device__ signed char        g_label[NB * TOTAL];
__device__ unsigned char      g_amax[NB * TOTAL];
__device__ int                g_cnt[4];             // [b*2 + isbg] candidate counts
__device__ unsigned int       g_hist[4 * NBINS];
__device__ unsigned int       g_csum[64];           // chunk sums for upd0
__device__ unsigned int       g_bin[4];             // selected 16-bit bin per group
__device__ int                g_m[4];               // rank within selected bin (1-based)
__device__ int                g_act[4];             // 0 => keep all candidates
__device__ int                g_ncand[4];
__device__ unsigned long long g_cand[4 * CAP];
__device__ unsigned long long g_thresh[4];          // exact m-th largest key (0 => keep all)
__device__ int                g_done_u;
__device__ int                g_done_c;
__device__ float              g_wval;

// IoU with strict _rn intrinsics so passA and passB are bitwise identical.
__device__ __forceinline__ float f_ov(float ax1, float ay1, float ax2, float ay2,
                                      float az1, float az2, float aarea,
                                      const float* __restrict__ g) {
    float iw = __fadd_rn(__fsub_rn(fminf(ax2, g[2]), fmaxf(ax1, g[0])), 1.0f);
    if (iw <= 0.0f) return 0.0f;
    float ih = __fadd_rn(__fsub_rn(fminf(ay2, g[3]), fmaxf(ay1, g[1])), 1.0f);
    if (ih <= 0.0f) return 0.0f;
    float idp = __fadd_rn(__fsub_rn(fminf(az2, g[5]), fmaxf(az1, g[4])), 1.0f);
    if (idp <= 0.0f) return 0.0f;
    float inter = __fmul_rn(__fmul_rn(iw, ih), idp);
    float den   = __fsub_rn(__fadd_rn(aarea, g[6]), inter);
    return __fdiv_rn(inter, den);
}

__device__ __forceinline__ float f_area(float x1, float y1, float x2, float y2,
                                        float z1, float z2) {
    float aw = __fadd_rn(__fsub_rn(x2, x1), 1.0f);
    float ah = __fadd_rn(__fsub_rn(y2, y1), 1.0f);
    float ad = __fadd_rn(__fsub_rn(z2, z1), 1.0f);
    return __fmul_rn(__fmul_rn(aw, ah), ad);
}

// ---------------- k_init: tables + state reset (1 block) ----------------
__global__ void __launch_bounds__(256) k_init(const float* __restrict__ gt,
                                              const float* __restrict__ anchors) {
    int t = threadIdx.x;
    if (t < NB * NK) {
        const float* g = gt + t * 7;
        float x1 = g[0], y1 = g[1], x2 = g[2], y2 = g[3], z1 = g[4], z2 = g[5];
        float gw = __fadd_rn(__fsub_rn(x2, x1), 1.0f);
        float gh = __fadd_rn(__fsub_rn(y2, y1), 1.0f);
        float gd = __fadd_rn(__fsub_rn(z2, z1), 1.0f);
        // derived (use original coords)
        float* gd6 = g_gtd + t * 6;
        gd6[0] = x1 + 0.5f * (gw - 1.0f);
        gd6[1] = y1 + 0.5f * (gh - 1.0f);
        gd6[2] = z1 + 0.5f * (gd - 1.0f);
        gd6[3] = logf(gw);
        gd6[4] = logf(gh);
        gd6[5] = logf(gd);
        // raw for IoU (zero-size gt => force ov = 0 via impossible box)
        if (gw == 1.0f && gh == 1.0f && gd == 1.0f) { x2 = -1e9f; }
        float* o = g_gt + t * 7;
        o[0] = x1; o[1] = y1; o[2] = x2; o[3] = y2; o[4] = z1; o[5] = z2;
        o[6] = __fmul_rn(__fmul_rn(gw, gh), gd);
        g_gtmax[t] = __float_as_int(-1.0f);
    }
    if (t >= 64 && t < 64 + NA) {
        int a = t - 64;
        const float* an = anchors + a * 6;
        float ew = an[2] - an[0] + 1.0f;
        float eh = an[3] - an[1] + 1.0f;
        float ed = an[5] - an[4] + 1.0f;
        float* o = g_ancd + a * 9;
        o[0] = an[0] + 0.5f * (ew - 1.0f);
        o[1] = an[1] + 0.5f * (eh - 1.0f);
        o[2] = an[4] + 0.5f * (ed - 1.0f);
        o[3] = 1.0f / ew; o[4] = 1.0f / eh; o[5] = 1.0f / ed;
        o[6] = logf(ew); o[7] = logf(eh); o[8] = logf(ed);
    }
    if (t >= 128 && t < 132) {
        int g = t - 128;
        g_cnt[g] = 0; g_ncand[g] = 0; g_act[g] = 1;
        g_thresh[g] = 0ULL; g_m[g] = 0; g_bin[g] = 0u;
    }
    if (t == 132) { g_done_u = 0; g_done_c = 0; }
}

// ---------------- passA: hist zero + gt_max over inside anchors ----------------
__global__ void __launch_bounds__(256) k_passA(const float* __restrict__ anchors,
                                               const float* __restrict__ im_info) {
    // zero the histogram (4*NBINS words = 65536 uint4)
    {
        int z = blockIdx.x * 256 + threadIdx.x;
        if (z < 65536) ((uint4*)g_hist)[z] = make_uint4(0u, 0u, 0u, 0u);
    }
    int b    = blockIdx.x / BPB;
    int base = (blockIdx.x % BPB) * 2048;
    __shared__ float sgt[NK * 7];
    __shared__ float sanch[NA * 6];
    __shared__ float red[8][NK];
    for (int j = threadIdx.x; j < NK * 7; j += 256) sgt[j] = g_gt[b * NK * 7 + j];
    if (threadIdx.x < NA * 6) sanch[threadIdx.x] = anchors[threadIdx.x];
    __syncthreads();
    float iH = im_info[0], iW = im_info[1], iD = im_info[2];

    float vmax[NK];
#pragma unroll
    for (int k = 0; k < NK; k++) vmax[k] = -1.0f;

    for (int t = 0; t < 8; t++) {
        int i = base + t * 256 + threadIdx.x;
        int a = i % NA; int q = i / NA;
        int d = q % ND; q /= ND;
        int w = q % NW; int h = q / NW;
        float shx = w * 16.0f, shy = h * 16.0f, shz = d * 16.0f;
        const float* an = sanch + a * 6;
        float ax1 = an[0] + shx, ay1 = an[1] + shy;
        float ax2 = an[2] + shx, ay2 = an[3] + shy;
        float az1 = an[4] + shz, az2 = an[5] + shz;
        bool inside = (ax1 >= 0.0f) && (ay1 >= 0.0f) && (az1 >= 0.0f) &&
                      (ax2 < iW) && (ay2 < iH) && (az2 < iD);
        if (!inside) continue;
        float aarea = f_area(ax1, ay1, ax2, ay2, az1, az2);
#pragma unroll
        for (int k = 0; k < NK; k++) {
            float ov = f_ov(ax1, ay1, ax2, ay2, az1, az2, aarea, sgt + k * 7);
            vmax[k] = fmaxf(vmax[k], ov);
        }
    }
    int lane = threadIdx.x & 31, wid = threadIdx.x >> 5;
#pragma unroll
    for (int k = 0; k < NK; k++) {
        float v = vmax[k];
#pragma unroll
        for (int off = 16; off; off >>= 1) v = fmaxf(v, __shfl_xor_sync(0xFFFFFFFFu, v, off));
        if (lane == 0) red[wid][k] = v;
    }
    __syncthreads();
    if (threadIdx.x < NK) {
        float m = red[0][threadIdx.x];
#pragma unroll
        for (int wq = 1; wq < 8; wq++) m = fmaxf(m, red[wq][threadIdx.x]);
        atomicMax(&g_gtmax[b * NK + threadIdx.x], __float_as_int(m));
    }
}

// ---------------- passB: labels, argmax, hist, counts ----------------
__global__ void __launch_bounds__(256) k_passB(const float* __restrict__ anchors,
                                               const float* __restrict__ im_info,
                                               const float* __restrict__ rfg,
                                               const float* __restrict__ rbg) {
    int b    = blockIdx.x / BPB;
    int base = (blockIdx.x % BPB) * 2048;
    __shared__ float sgt[NK * 7];
    __shared__ float sgm[NK];
    __shared__ float sanch[NA * 6];
    __shared__ int   scnt[2];
    for (int j = threadIdx.x; j < NK * 7; j += 256) sgt[j] = g_gt[b * NK * 7 + j];
    if (threadIdx.x < NK) {
        float gm = __int_as_float(g_gtmax[b * NK + threadIdx.x]);
        sgm[threadIdx.x] = (gm == 0.0f) ? 1e-5f : gm;
    }
    if (threadIdx.x < NA * 6) sanch[threadIdx.x] = anchors[threadIdx.x];
    if (threadIdx.x < 2) scnt[threadIdx.x] = 0;
    __syncthreads();
    float iH = im_info[0], iW = im_info[1], iD = im_info[2];
    int lane = threadIdx.x & 31;

    for (int t = 0; t < 8; t++) {
        int i = base + t * 256 + threadIdx.x;
        int e = b * TOTAL + i;
        int a = i % NA; int q = i / NA;
        int d = q % ND; q /= ND;
        int w = q % NW; int h = q / NW;
        float shx = w * 16.0f, shy = h * 16.0f, shz = d * 16.0f;
        const float* an = sanch + a * 6;
        float ax1 = an[0] + shx, ay1 = an[1] + shy;
        float ax2 = an[2] + shx, ay2 = an[3] + shy;
        float az1 = an[4] + shz, az2 = an[5] + shz;
        bool inside = (ax1 >= 0.0f) && (ay1 >= 0.0f) && (az1 >= 0.0f) &&
                      (ax2 < iW) && (ay2 < iH) && (az2 < iD);
        signed char lab = -1;
        unsigned char am = 0;
        if (inside) {
            float aarea = f_area(ax1, ay1, ax2, ay2, az1, az2);
            float best = -1.0f;
            int bi = 0;
            bool tie = false;
#pragma unroll
            for (int k = 0; k < NK; k++) {
                float ov = f_ov(ax1, ay1, ax2, ay2, az1, az2, aarea, sgt + k * 7);
                if (ov > best) { best = ov; bi = k; }
                if (ov == sgm[k]) tie = true;
            }
            lab = (tie || best >= 0.7f) ? 1 : ((best < 0.3f) ? 0 : -1);
            am = (unsigned char)bi;
        }
        g_label[e] = lab;
        g_amax[e]  = am;

        unsigned b1 = __ballot_sync(0xFFFFFFFFu, lab == 1);
        unsigned b0 = __ballot_sync(0xFFFFFFFFu, lab == 0);
        if (lane == 0) {
            if (b1) atomicAdd(&scnt[0], __popc(b1));
            if (b0) atomicAdd(&scnt[1], __popc(b0));
        }
        if (lab == 1) {
            unsigned bin = __float_as_uint(rfg[e]) >> 16;
            atomicAdd(&g_hist[(b * 2) * NBINS + bin], 1u);
        } else if (lab == 0) {
            unsigned bin = __float_as_uint(rbg[e]) >> 16;
            atomicAdd(&g_hist[(b * 2 + 1) * NBINS + bin], 1u);
        }
    }
    __syncthreads();
    if (threadIdx.x < 2 && scnt[threadIdx.x]) atomicAdd(&g_cnt[b * 2 + threadIdx.x], scnt[threadIdx.x]);
}

// ---------------- upd0: chunk sums (64 blocks) + last-block bin resolve ----------------
__global__ void __launch_bounds__(256) k_upd0() {
    int grp   = blockIdx.x >> 4;
    int chunk = blockIdx.x & 15;
    int lane = threadIdx.x & 31, wid = threadIdx.x >> 5;
    const unsigned* hist = g_hist + grp * NBINS;

    // chunk sum: 4096 bins, coalesced uint4 loads
    const uint4* hp = (const uint4*)(hist + chunk * 4096);
    unsigned s = 0;
#pragma unroll
    for (int j = 0; j < 4; j++) {
        uint4 v = hp[j * 256 + threadIdx.x];
        s += v.x + v.y + v.z + v.w;
    }
#pragma unroll
    for (int off = 16; off; off >>= 1) s += __shfl_xor_sync(0xFFFFFFFFu, s, off);
    __shared__ unsigned ws[8];
    __shared__ int slast;
    if (lane == 0) ws[wid] = s;
    __syncthreads();
    if (threadIdx.x == 0) {
        unsigned tot = 0;
#pragma unroll
        for (int i = 0; i < 8; i++) tot += ws[i];
        g_csum[grp * 16 + chunk] = tot;
        __threadfence();
        int o = atomicAdd(&g_done_u, 1);
        slast = (o == 63) ? 1 : 0;
    }
    __syncthreads();
    if (!slast) return;

    // last block: resolve threshold bin for all 4 groups
    __shared__ unsigned sb[4096];
    for (int g2 = 0; g2 < 4; g2++) {
        int m0;
        if ((g2 & 1) == 0) m0 = NUMFG;
        else { int fgc = g_cnt[g2 - 1]; int kept = (fgc < NUMFG) ? fgc : NUMFG; m0 = RPNB - kept; }
        if (g2 == 3 && threadIdx.x == 0) {
            int fg1 = g_cnt[2]; if (fg1 > NUMFG) fg1 = NUMFG;
            int cap = RPNB - fg1;
            int bg1 = g_cnt[3]; if (bg1 > cap) bg1 = cap;
            int ne = fg1 + bg1;
            g_wval = 1.0f / (float)(ne > 0 ? ne : 1);
        }
        unsigned cs[16];
        unsigned total = 0;
#pragma unroll
        for (int c = 0; c < 16; c++) { cs[c] = g_csum[g2 * 16 + c]; total += cs[c]; }
        if ((unsigned)m0 >= total) {
            if (threadIdx.x == 0) g_act[g2] = 0;
            continue;
        }
        // find crossing chunk scanning from the top
        int cstar = 0; unsigned acc = 0;
        for (int c = 15; c >= 0; c--) {
            if (acc + cs[c] >= (unsigned)m0) { cstar = c; break; }
            acc += cs[c];
        }
        int m_rem = m0 - (int)acc;   // rank from top within chunk, >= 1
        // load chunk to smem
        const unsigned* hb = g_hist + g2 * NBINS + cstar * 4096;
        for (int i = threadIdx.x; i < 4096; i += 256) sb[i] = hb[i];
        __syncthreads();
        if (threadIdx.x < 32) {
            unsigned accw = 0;
            for (int basei = 4095; basei >= 31; basei -= 32) {
                unsigned v = sb[basei - lane];           // lane 0 = highest bin
                unsigned inc = v;
#pragma unroll
                for (int off = 1; off < 32; off <<= 1) {
                    unsigned u = __shfl_up_sync(0xFFFFFFFFu, inc, off);
                    if (lane >= off) inc += u;
                }
                unsigned tot32 = __shfl_sync(0xFFFFFFFFu, inc, 31);
                if (accw + tot32 >= (unsigned)m_rem) {
                    unsigned incl = accw + inc;
                    unsigned excl = incl - v;
                    if (excl < (unsigned)m_rem && (unsigned)m_rem <= incl) {
                        g_bin[g2] = (unsigned)(cstar * 4096 + basei - lane);
                        g_m[g2]   = m_rem - (int)excl;   // 1-based rank within bin
                    }
                    break;
                }
                accw += tot32;
            }
        }
        __syncthreads();
    }
}

// ---------------- collect + last-block exact threshold ----------------
__global__ void __launch_bounds__(256) k_collect(const float* __restrict__ rfg,
                                                 const float* __restrict__ rbg) {
    int e = blockIdx.x * 256 + threadIdx.x;
    int lab = g_label[e];
    if (lab >= 0) {
        int b = (e >= TOTAL) ? 1 : 0;
        unsigned i = (unsigned)(e - b * TOTAL);
        int grp = b * 2 + (lab == 0 ? 1 : 0);
        if (g_act[grp]) {
            float rv = (lab == 1) ? rfg[e] : rbg[e];
            unsigned rb = __float_as_uint(rv);
            if ((rb >> 16) == g_bin[grp]) {
                unsigned long long key = ((unsigned long long)rb << 32) | (unsigned)(~i);
                int pos = atomicAdd(&g_ncand[grp], 1);
                if (pos < CAP) g_cand[grp * CAP + pos] = key;
            }
        }
    }
    __threadfence();
    __syncthreads();
    __shared__ int slast;
    if (threadIdx.x == 0) {
        int o = atomicAdd(&g_done_c, 1);
        slast = (o == (int)gridDim.x - 1) ? 1 : 0;
    }
    __syncthreads();
    if (!slast) return;

    __shared__ unsigned long long sk[CAP];
    for (int grp = 0; grp < 4; grp++) {
        if (!g_act[grp]) continue;
        int n = g_ncand[grp]; if (n > CAP) n = CAP;
        int m = g_m[grp];
        for (int i = threadIdx.x; i < n; i += 256) sk[i] = g_cand[grp * CAP + i];
        __syncthreads();
        for (int i = threadIdx.x; i < n; i += 256) {
            unsigned long long k = sk[i];
            int cg = 0;
            for (int j = 0; j < n; j++) cg += (sk[j] > k) ? 1 : 0;
            if (cg == m - 1) g_thresh[grp] = k;
        }
        __syncthreads();
    }
}

// ---------------- passD: final labels + all outputs, float4 stores ----------------
__global__ void __launch_bounds__(256) k_passD(const float* __restrict__ anchors,
                                               const float* __restrict__ im_info,
                                               const float* __restrict__ rfg,
                                               const float* __restrict__ rbg,
                                               float* __restrict__ out) {
    int tid = blockIdx.x * 256 + threadIdx.x;
    int idx = tid * 4;
    int d0 = idx % ND; int q = idx / ND;
    int w = q % NW; q /= NW;
    int h = q % NH; q /= NH;
    int a = q % NA; int b = q / NA;
    int pix0 = (h * NW + w) * ND + d0;

    __shared__ float sanch[NA * 6];
    __shared__ float sder[NA * 9];
    __shared__ float sgtd[NB * NK * 6];
    __shared__ unsigned long long sth[4];
    if (threadIdx.x < NA * 6) sanch[threadIdx.x] = anchors[threadIdx.x];
    if (threadIdx.x < NA * 9) sder[threadIdx.x] = g_ancd[threadIdx.x];
    if (threadIdx.x < NB * NK * 6) sgtd[threadIdx.x] = g_gtd[threadIdx.x];
    if (threadIdx.x < 4) sth[threadIdx.x] = g_thresh[threadIdx.x];
    __syncthreads();

    const float* an = sanch + a * 6;
    const float* ad = sder + a * 9;
    float shx = w * 16.0f, shy = h * 16.0f;
    float ax1 = an[0] + shx, ay1 = an[1] + shy;
    float ax2 = an[2] + shx, ay2 = an[3] + shy;
    float iH = im_info[0], iW = im_info[1], iD = im_info[2];
    bool inxy = (ax1 >= 0.0f) && (ay1 >= 0.0f) && (ax2 < iW) && (ay2 < iH);
    float wv = g_wval;

    float lb[4], ivv[4], ovv[4];
    float T[6][4];
#pragma unroll
    for (int j = 0; j < 4; j++) {
        float shz = (float)(d0 + j) * 16.0f;
        float az1 = an[4] + shz, az2 = an[5] + shz;
        bool inside = inxy && (az1 >= 0.0f) && (az2 < iD);
        int ia = (pix0 + j) * NA + a;
        int e  = b * TOTAL + ia;
        int lab = (int)g_label[e];
        if (lab >= 0) {
            int grp = b * 2 + (lab == 0 ? 1 : 0);
            float rv = (lab == 1) ? rfg[e] : rbg[e];
            unsigned long long key = ((unsigned long long)__float_as_uint(rv) << 32) | (unsigned)(~(unsigned)ia);
            if (key < sth[grp]) lab = -1;
        }
        float t0 = 0.0f, t1 = 0.0f, t2 = 0.0f, t3 = 0.0f, t4 = 0.0f, t5 = 0.0f;
        if (inside) {
            int am = (int)g_amax[e];
            const float* gd = sgtd + (b * NK + am) * 6;
            t0 = (gd[0] - ad[0] - shx) * ad[3];
            t1 = (gd[1] - ad[1] - shy) * ad[4];
            t2 = (gd[2] - ad[2] - shz) * ad[5];
            t3 = gd[3] - ad[6];
            t4 = gd[4] - ad[7];
            t5 = gd[5] - ad[8];
        }
        T[0][j] = t0; T[1][j] = t1; T[2][j] = t2;
        T[3][j] = t3; T[4][j] = t4; T[5][j] = t5;
        lb[j]  = (float)lab;
        ivv[j] = (lab == 1) ? 1.0f : 0.0f;
        ovv[j] = (lab >= 0) ? wv : 0.0f;
    }

    *(float4*)(out + idx) = make_float4(lb[0], lb[1], lb[2], lb[3]);
    long long base = (long long)(b * 54 + a * 6) * HWD + pix0;
    float* bt = out + OFF_BT + base;
#pragma unroll
    for (int c = 0; c < 6; c++)
        *(float4*)(bt + c * HWD) = make_float4(T[c][0], T[c][1], T[c][2], T[c][3]);
    float* iwp = out + OFF_IW + base;
    float* owp = out + OFF_OW + base;
    float4 iv = make_float4(ivv[0], ivv[1], ivv[2], ivv[3]);
    float4 ov = make_float4(ovv[0], ovv[1], ovv[2], ovv[3]);
#pragma unroll
    for (int c = 0; c < 6; c++) {
        *(float4*)(iwp + c * HWD) = iv;
        *(float4*)(owp + c * HWD) = ov;
    }
}

// ---------------- launch ----------------
extern "C" void kernel_launch(void* const* d_in, const int* in_sizes, int n_in,
                              void* d_out, int out_size) {
    const float* gt      = (const float*)d_in[1];
    const float* im_info = (const float*)d_in[2];
    const float* anchors = (const float*)d_in[4];
    const float* rfg     = (const float*)d_in[5];
    const float* rbg     = (const float*)d_in[6];
    float* out           = (float*)d_out;

    k_init<<<1, 256>>>(gt, anchors);
    k_passA<<<NB * BPB, 256>>>(anchors, im_info);
    k_passB<<<NB * BPB, 256>>>(anchors, im_info, rfg, rbg);
    k_upd0<<<64, 256>>>();
    k_collect<<<(NB * TOTAL) / 256, 256>>>(rfg, rbg);
    k_passD<<<OUTTOT / 4 / 256, 256>>>(anchors, im_info, rfg, rbg, out);
}

// round 6
// speedup vs baseline: 1.2070x; 1.2070x over previous
#include <cuda_runtime.h>
#include <cuda_bf16.h>
#include <stdint.h>

#define NB 2
#define NH 48
#define NW 48
#define ND 24
#define NA 9
#define NK 20
#define TOTAL  497664            // NH*NW*ND*NA
#define HWD    55296             // NH*NW*ND
#define OUTTOT 995328            // NB*NA*HWD
#define NUMFG 128
#define RPNB  256
#define NBINS 65536
#define BPB   243                // blocks per batch in pass A/B (2048 anchors each)
#define CAP   4096               // per-group candidate buffer (threshold bin members)

#define OFF_BT  995328
#define OFF_IW  (OFF_BT + 5971968)
#define OFF_OW  (OFF_IW + 5971968)

// ---------------- device scratch (no allocations allowed) ----------------
__device__ float              g_gt[NB * NK * 7];    // x1 y1 x2 y2 z1 z2 area (mangled for zero-size)
__device__ float              g_gtd[NB * NK * 6];   // gcx gcy gcz log(gw) log(gh) log(gd)
__device__ float              g_ancd[NA * 9];       // cxa cya cza 1/ew 1/eh 1/ed lew leh led
__device__ int                g_gtmax[NB * NK];     // float-as-int max IoU per gt
__device__ signed char        g_label[NB * TOTAL];
__device__ unsigned char      g_amax[NB * TOTAL];
__device__ int                g_cnt[4];             // [b*2 + isbg] candidate counts
__device__ unsigned int       g_hist[4 * NBINS];
__device__ unsigned int       g_csum[64];           // chunk sums for upd0
__device__ unsigned int       g_bin[4];             // selected 16-bit bin per group
__device__ int                g_m[4];               // rank within selected bin (1-based)
__device__ int                g_act[4];             // 0 => keep all candidates
__device__ int                g_ncand[4];
__device__ unsigned long long g_cand[4 * CAP];
__device__ unsigned long long g_thresh[4];          // exact m-th largest key (0 => keep all)
__device__ int                g_done_u;
__device__ float              g_wval;

// IoU with strict _rn intrinsics so passA and passB are bitwise identical.
__device__ __forceinline__ float f_ov(float ax1, float ay1, float ax2, float ay2,
                                      float az1, float az2, float aarea,
                                      const float* __restrict__ g) {
    float iw = __fadd_rn(__fsub_rn(fminf(ax2, g[2]), fmaxf(ax1, g[0])), 1.0f);
    if (iw <= 0.0f) return 0.0f;
    float ih = __fadd_rn(__fsub_rn(fminf(ay2, g[3]), fmaxf(ay1, g[1])), 1.0f);
    if (ih <= 0.0f) return 0.0f;
    float idp = __fadd_rn(__fsub_rn(fminf(az2, g[5]), fmaxf(az1, g[4])), 1.0f);
    if (idp <= 0.0f) return 0.0f;
    float inter = __fmul_rn(__fmul_rn(iw, ih), idp);
    float den   = __fsub_rn(__fadd_rn(aarea, g[6]), inter);
    return __fdiv_rn(inter, den);
}

__device__ __forceinline__ float f_area(float x1, float y1, float x2, float y2,
                                        float z1, float z2) {
    float aw = __fadd_rn(__fsub_rn(x2, x1), 1.0f);
    float ah = __fadd_rn(__fsub_rn(y2, y1), 1.0f);
    float ad = __fadd_rn(__fsub_rn(z2, z1), 1.0f);
    return __fmul_rn(__fmul_rn(aw, ah), ad);
}

// ---------------- k_init: tables + state reset (1 block) ----------------
__global__ void __launch_bounds__(256) k_init(const float* __restrict__ gt,
                                              const float* __restrict__ anchors) {
    int t = threadIdx.x;
    if (t < NB * NK) {
        const float* g = gt + t * 7;
        float x1 = g[0], y1 = g[1], x2 = g[2], y2 = g[3], z1 = g[4], z2 = g[5];
        float gw = __fadd_rn(__fsub_rn(x2, x1), 1.0f);
        float gh = __fadd_rn(__fsub_rn(y2, y1), 1.0f);
        float gd = __fadd_rn(__fsub_rn(z2, z1), 1.0f);
        // derived (use original coords)
        float* gd6 = g_gtd + t * 6;
        gd6[0] = x1 + 0.5f * (gw - 1.0f);
        gd6[1] = y1 + 0.5f * (gh - 1.0f);
        gd6[2] = z1 + 0.5f * (gd - 1.0f);
        gd6[3] = logf(gw);
        gd6[4] = logf(gh);
        gd6[5] = logf(gd);
        // raw for IoU (zero-size gt => force ov = 0 via impossible box)
        if (gw == 1.0f && gh == 1.0f && gd == 1.0f) { x2 = -1e9f; }
        float* o = g_gt + t * 7;
        o[0] = x1; o[1] = y1; o[2] = x2; o[3] = y2; o[4] = z1; o[5] = z2;
        o[6] = __fmul_rn(__fmul_rn(gw, gh), gd);
        g_gtmax[t] = __float_as_int(-1.0f);
    }
    if (t >= 64 && t < 64 + NA) {
        int a = t - 64;
        const float* an = anchors + a * 6;
        float ew = an[2] - an[0] + 1.0f;
        float eh = an[3] - an[1] + 1.0f;
        float ed = an[5] - an[4] + 1.0f;
        float* o = g_ancd + a * 9;
        o[0] = an[0] + 0.5f * (ew - 1.0f);
        o[1] = an[1] + 0.5f * (eh - 1.0f);
        o[2] = an[4] + 0.5f * (ed - 1.0f);
        o[3] = 1.0f / ew; o[4] = 1.0f / eh; o[5] = 1.0f / ed;
        o[6] = logf(ew); o[7] = logf(eh); o[8] = logf(ed);
    }
    if (t >= 128 && t < 132) {
        int g = t - 128;
        g_cnt[g] = 0; g_ncand[g] = 0; g_act[g] = 1;
        g_thresh[g] = 0ULL; g_m[g] = 0; g_bin[g] = 0u;
    }
    if (t == 132) { g_done_u = 0; }
}

// ---------------- passA: hist zero + gt_max over inside anchors ----------------
__global__ void __launch_bounds__(256) k_passA(const float* __restrict__ anchors,
                                               const float* __restrict__ im_info) {
    // zero the histogram (4*NBINS words = 65536 uint4)
    {
        int z = blockIdx.x * 256 + threadIdx.x;
        if (z < 65536) ((uint4*)g_hist)[z] = make_uint4(0u, 0u, 0u, 0u);
    }
    int b    = blockIdx.x / BPB;
    int base = (blockIdx.x % BPB) * 2048;
    __shared__ float sgt[NK * 7];
    __shared__ float sanch[NA * 6];
    __shared__ float red[8][NK];
    for (int j = threadIdx.x; j < NK * 7; j += 256) sgt[j] = g_gt[b * NK * 7 + j];
    if (threadIdx.x < NA * 6) sanch[threadIdx.x] = anchors[threadIdx.x];
    __syncthreads();
    float iH = im_info[0], iW = im_info[1], iD = im_info[2];

    float vmax[NK];
#pragma unroll
    for (int k = 0; k < NK; k++) vmax[k] = -1.0f;

    for (int t = 0; t < 8; t++) {
        int i = base + t * 256 + threadIdx.x;
        int a = i % NA; int q = i / NA;
        int d = q % ND; q /= ND;
        int w = q % NW; int h = q / NW;
        float shx = w * 16.0f, shy = h * 16.0f, shz = d * 16.0f;
        const float* an = sanch + a * 6;
        float ax1 = an[0] + shx, ay1 = an[1] + shy;
        float ax2 = an[2] + shx, ay2 = an[3] + shy;
        float az1 = an[4] + shz, az2 = an[5] + shz;
        bool inside = (ax1 >= 0.0f) && (ay1 >= 0.0f) && (az1 >= 0.0f) &&
                      (ax2 < iW) && (ay2 < iH) && (az2 < iD);
        if (!inside) continue;
        float aarea = f_area(ax1, ay1, ax2, ay2, az1, az2);
#pragma unroll
        for (int k = 0; k < NK; k++) {
            float ov = f_ov(ax1, ay1, ax2, ay2, az1, az2, aarea, sgt + k * 7);
            vmax[k] = fmaxf(vmax[k], ov);
        }
    }
    int lane = threadIdx.x & 31, wid = threadIdx.x >> 5;
#pragma unroll
    for (int k = 0; k < NK; k++) {
        float v = vmax[k];
#pragma unroll
        for (int off = 16; off; off >>= 1) v = fmaxf(v, __shfl_xor_sync(0xFFFFFFFFu, v, off));
        if (lane == 0) red[wid][k] = v;
    }
    __syncthreads();
    if (threadIdx.x < NK) {
        float m = red[0][threadIdx.x];
#pragma unroll
        for (int wq = 1; wq < 8; wq++) m = fmaxf(m, red[wq][threadIdx.x]);
        atomicMax(&g_gtmax[b * NK + threadIdx.x], __float_as_int(m));
    }
}

// ---------------- passB: labels, argmax, hist, counts ----------------
__global__ void __launch_bounds__(256) k_passB(const float* __restrict__ anchors,
                                               const float* __restrict__ im_info,
                                               const float* __restrict__ rfg,
                                               const float* __restrict__ rbg) {
    int b    = blockIdx.x / BPB;
    int base = (blockIdx.x % BPB) * 2048;
    __shared__ float sgt[NK * 7];
    __shared__ float sgm[NK];
    __shared__ float sanch[NA * 6];
    __shared__ int   scnt[2];
    for (int j = threadIdx.x; j < NK * 7; j += 256) sgt[j] = g_gt[b * NK * 7 + j];
    if (threadIdx.x < NK) {
        float gm = __int_as_float(g_gtmax[b * NK + threadIdx.x]);
        sgm[threadIdx.x] = (gm == 0.0f) ? 1e-5f : gm;
    }
    if (threadIdx.x < NA * 6) sanch[threadIdx.x] = anchors[threadIdx.x];
    if (threadIdx.x < 2) scnt[threadIdx.x] = 0;
    __syncthreads();
    float iH = im_info[0], iW = im_info[1], iD = im_info[2];
    int lane = threadIdx.x & 31;

    for (int t = 0; t < 8; t++) {
        int i = base + t * 256 + threadIdx.x;
        int e = b * TOTAL + i;
        int a = i % NA; int q = i / NA;
        int d = q % ND; q /= ND;
        int w = q % NW; int h = q / NW;
        float shx = w * 16.0f, shy = h * 16.0f, shz = d * 16.0f;
        const float* an = sanch + a * 6;
        float ax1 = an[0] + shx, ay1 = an[1] + shy;
        float ax2 = an[2] + shx, ay2 = an[3] + shy;
        float az1 = an[4] + shz, az2 = an[5] + shz;
        bool inside = (ax1 >= 0.0f) && (ay1 >= 0.0f) && (az1 >= 0.0f) &&
                      (ax2 < iW) && (ay2 < iH) && (az2 < iD);
        signed char lab = -1;
        unsigned char am = 0;
        if (inside) {
            float aarea = f_area(ax1, ay1, ax2, ay2, az1, az2);
            float best = -1.0f;
            int bi = 0;
            bool tie = false;
#pragma unroll
            for (int k = 0; k < NK; k++) {
                float ov = f_ov(ax1, ay1, ax2, ay2, az1, az2, aarea, sgt + k * 7);
                if (ov > best) { best = ov; bi = k; }
                if (ov == sgm[k]) tie = true;
            }
            lab = (tie || best >= 0.7f) ? 1 : ((best < 0.3f) ? 0 : -1);
            am = (unsigned char)bi;
        }
        g_label[e] = lab;
        g_amax[e]  = am;

        unsigned b1 = __ballot_sync(0xFFFFFFFFu, lab == 1);
        unsigned b0 = __ballot_sync(0xFFFFFFFFu, lab == 0);
        if (lane == 0) {
            if (b1) atomicAdd(&scnt[0], __popc(b1));
            if (b0) atomicAdd(&scnt[1], __popc(b0));
        }
        if (lab == 1) {
            unsigned bin = __float_as_uint(rfg[e]) >> 16;
            atomicAdd(&g_hist[(b * 2) * NBINS + bin], 1u);
        } else if (lab == 0) {
            unsigned bin = __float_as_uint(rbg[e]) >> 16;
            atomicAdd(&g_hist[(b * 2 + 1) * NBINS + bin], 1u);
        }
    }
    __syncthreads();
    if (threadIdx.x < 2 && scnt[threadIdx.x]) atomicAdd(&g_cnt[b * 2 + threadIdx.x], scnt[threadIdx.x]);
}

// ---------------- upd0: chunk sums (64 blocks) + last-block bin resolve ----------------
__global__ void __launch_bounds__(256) k_upd0() {
    int grp   = blockIdx.x >> 4;
    int chunk = blockIdx.x & 15;
    int lane = threadIdx.x & 31, wid = threadIdx.x >> 5;
    const unsigned* hist = g_hist + grp * NBINS;

    // chunk sum: 4096 bins, coalesced uint4 loads
    const uint4* hp = (const uint4*)(hist + chunk * 4096);
    unsigned s = 0;
#pragma unroll
    for (int j = 0; j < 4; j++) {
        uint4 v = hp[j * 256 + threadIdx.x];
        s += v.x + v.y + v.z + v.w;
    }
#pragma unroll
    for (int off = 16; off; off >>= 1) s += __shfl_xor_sync(0xFFFFFFFFu, s, off);
    __shared__ unsigned ws[8];
    __shared__ int slast;
    if (lane == 0) ws[wid] = s;
    __syncthreads();
    if (threadIdx.x == 0) {
        unsigned tot = 0;
#pragma unroll
        for (int i = 0; i < 8; i++) tot += ws[i];
        g_csum[grp * 16 + chunk] = tot;
        __threadfence();
        int o = atomicAdd(&g_done_u, 1);
        slast = (o == 63) ? 1 : 0;
    }
    __syncthreads();
    if (!slast) return;

    // last block: resolve threshold bin for all 4 groups
    __shared__ unsigned sb[4096];
    for (int g2 = 0; g2 < 4; g2++) {
        int m0;
        if ((g2 & 1) == 0) m0 = NUMFG;
        else { int fgc = g_cnt[g2 - 1]; int kept = (fgc < NUMFG) ? fgc : NUMFG; m0 = RPNB - kept; }
        if (g2 == 3 && threadIdx.x == 0) {
            int fg1 = g_cnt[2]; if (fg1 > NUMFG) fg1 = NUMFG;
            int cap = RPNB - fg1;
            int bg1 = g_cnt[3]; if (bg1 > cap) bg1 = cap;
            int ne = fg1 + bg1;
            g_wval = 1.0f / (float)(ne > 0 ? ne : 1);
        }
        unsigned cs[16];
        unsigned total = 0;
#pragma unroll
        for (int c = 0; c < 16; c++) { cs[c] = g_csum[g2 * 16 + c]; total += cs[c]; }
        if ((unsigned)m0 >= total) {
            if (threadIdx.x == 0) g_act[g2] = 0;
            continue;
        }
        // find crossing chunk scanning from the top
        int cstar = 0; unsigned acc = 0;
        for (int c = 15; c >= 0; c--) {
            if (acc + cs[c] >= (unsigned)m0) { cstar = c; break; }
            acc += cs[c];
        }
        int m_rem = m0 - (int)acc;   // rank from top within chunk, >= 1
        // load chunk to smem
        const unsigned* hb = g_hist + g2 * NBINS + cstar * 4096;
        for (int i = threadIdx.x; i < 4096; i += 256) sb[i] = hb[i];
        __syncthreads();
        if (threadIdx.x < 32) {
            unsigned accw = 0;
            for (int basei = 4095; basei >= 31; basei -= 32) {
                unsigned v = sb[basei - lane];           // lane 0 = highest bin
                unsigned inc = v;
#pragma unroll
                for (int off = 1; off < 32; off <<= 1) {
                    unsigned u = __shfl_up_sync(0xFFFFFFFFu, inc, off);
                    if (lane >= off) inc += u;
                }
                unsigned tot32 = __shfl_sync(0xFFFFFFFFu, inc, 31);
                if (accw + tot32 >= (unsigned)m_rem) {
                    unsigned incl = accw + inc;
                    unsigned excl = incl - v;
                    if (excl < (unsigned)m_rem && (unsigned)m_rem <= incl) {
                        g_bin[g2] = (unsigned)(cstar * 4096 + basei - lane);
                        g_m[g2]   = m_rem - (int)excl;   // 1-based rank within bin
                    }
                    break;
                }
                accw += tot32;
            }
        }
        __syncthreads();
    }
}

// ---------------- collect: gather keys in the threshold bin ----------------
__global__ void __launch_bounds__(256) k_collect(const float* __restrict__ rfg,
                                                 const float* __restrict__ rbg) {
    int e = blockIdx.x * 256 + threadIdx.x;
    int lab = g_label[e];
    if (lab < 0) return;
    int b = (e >= TOTAL) ? 1 : 0;
    unsigned i = (unsigned)(e - b * TOTAL);
    int grp = b * 2 + (lab == 0 ? 1 : 0);
    if (!g_act[grp]) return;
    float rv = (lab == 1) ? rfg[e] : rbg[e];
    unsigned rb = __float_as_uint(rv);
    if ((rb >> 16) != g_bin[grp]) return;
    unsigned long long key = ((unsigned long long)rb << 32) | (unsigned)(~i);
    int pos = atomicAdd(&g_ncand[grp], 1);
    if (pos < CAP) g_cand[grp * CAP + pos] = key;
}

// ---------------- finish: exact m-th largest within the bin ----------------
__global__ void __launch_bounds__(256) k_finish() {
    int grp = blockIdx.x;
    if (!g_act[grp]) return;      // thresh already 0
    __shared__ unsigned long long sk[CAP];
    int n = g_ncand[grp];
    if (n > CAP) n = CAP;
    int m = g_m[grp];             // 1-based rank
    for (int i = threadIdx.x; i < n; i += 256) sk[i] = g_cand[grp * CAP + i];
    __syncthreads();
    for (int i = threadIdx.x; i < n; i += 256) {
        unsigned long long k = sk[i];
        int cg = 0;
        for (int j = 0; j < n; j++) cg += (sk[j] > k) ? 1 : 0;
        if (cg == m - 1) g_thresh[grp] = k;
    }
}

// ---------------- passD: final labels + all outputs, float4 stores ----------------
__global__ void __launch_bounds__(256) k_passD(const float* __restrict__ anchors,
                                               const float* __restrict__ im_info,
                                               const float* __restrict__ rfg,
                                               const float* __restrict__ rbg,
                                               float* __restrict__ out) {
    int tid = blockIdx.x * 256 + threadIdx.x;
    int idx = tid * 4;
    int d0 = idx % ND; int q = idx / ND;
    int w = q % NW; q /= NW;
    int h = q % NH; q /= NH;
    int a = q % NA; int b = q / NA;
    int pix0 = (h * NW + w) * ND + d0;

    __shared__ float sanch[NA * 6];
    __shared__ float sder[NA * 9];
    __shared__ float sgtd[NB * NK * 6];
    __shared__ unsigned long long sth[4];
    if (threadIdx.x < NA * 6) sanch[threadIdx.x] = anchors[threadIdx.x];
    if (threadIdx.x < NA * 9) sder[threadIdx.x] = g_ancd[threadIdx.x];
    if (threadIdx.x < NB * NK * 6) sgtd[threadIdx.x] = g_gtd[threadIdx.x];
    if (threadIdx.x < 4) sth[threadIdx.x] = g_thresh[threadIdx.x];
    __syncthreads();

    const float* an = sanch + a * 6;
    const float* ad = sder + a * 9;
    float shx = w * 16.0f, shy = h * 16.0f;
    float ax1 = an[0] + shx, ay1 = an[1] + shy;
    float ax2 = an[2] + shx, ay2 = an[3] + shy;
    float iH = im_info[0], iW = im_info[1], iD = im_info[2];
    bool inxy = (ax1 >= 0.0f) && (ay1 >= 0.0f) && (ax2 < iW) && (ay2 < iH);
    float wv = g_wval;

    float lb[4], ivv[4], ovv[4];
    float T[6][4];
#pragma unroll
    for (int j = 0; j < 4; j++) {
        float shz = (float)(d0 + j) * 16.0f;
        float az1 = an[4] + shz, az2 = an[5] + shz;
        bool inside = inxy && (az1 >= 0.0f) && (az2 < iD);
        int ia = (pix0 + j) * NA + a;
        int e  = b * TOTAL + ia;
        int lab = (int)g_label[e];
        if (lab >= 0) {
            int grp = b * 2 + (lab == 0 ? 1 : 0);
            float rv = (lab == 1) ? rfg[e] : rbg[e];
            unsigned long long key = ((unsigned long long)__float_as_uint(rv) << 32) | (unsigned)(~(unsigned)ia);
            if (key < sth[grp]) lab = -1;
        }
        float t0 = 0.0f, t1 = 0.0f, t2 = 0.0f, t3 = 0.0f, t4 = 0.0f, t5 = 0.0f;
        if (inside) {
            int am = (int)g_amax[e];
            const float* gd = sgtd + (b * NK + am) * 6;
            t0 = (gd[0] - ad[0] - shx) * ad[3];
            t1 = (gd[1] - ad[1] - shy) * ad[4];
            t2 = (gd[2] - ad[2] - shz) * ad[5];
            t3 = gd[3] - ad[6];
            t4 = gd[4] - ad[7];
            t5 = gd[5] - ad[8];
        }
        T[0][j] = t0; T[1][j] = t1; T[2][j] = t2;
        T[3][j] = t3; T[4][j] = t4; T[5][j] = t5;
        lb[j]  = (float)lab;
        ivv[j] = (lab == 1) ? 1.0f : 0.0f;
        ovv[j] = (lab >= 0) ? wv : 0.0f;
    }

    *(float4*)(out + idx) = make_float4(lb[0], lb[1], lb[2], lb[3]);
    long long base = (long long)(b * 54 + a * 6) * HWD + pix0;
    float* bt = out + OFF_BT + base;
#pragma unroll
    for (int c = 0; c < 6; c++)
        *(float4*)(bt + c * HWD) = make_float4(T[c][0], T[c][1], T[c][2], T[c][3]);
    float* iwp = out + OFF_IW + base;
    float* owp = out + OFF_OW + base;
    float4 iv = make_float4(ivv[0], ivv[1], ivv[2], ivv[3]);
    float4 ov = make_float4(ovv[0], ovv[1], ovv[2], ovv[3]);
#pragma unroll
    for (int c = 0; c < 6; c++) {
        *(float4*)(iwp + c * HWD) = iv;
        *(float4*)(owp + c * HWD) = ov;
    }
}

// ---------------- launch ----------------
extern "C" void kernel_launch(void* const* d_in, const int* in_sizes, int n_in,
                              void* d_out, int out_size) {
    const float* gt      = (const float*)d_in[1];
    const float* im_info = (const float*)d_in[2];
    const float* anchors = (const float*)d_in[4];
    const float* rfg     = (const float*)d_in[5];
    const float* rbg     = (const float*)d_in[6];
    float* out           = (float*)d_out;

    k_init<<<1, 256>>>(gt, anchors);
    k_passA<<<NB * BPB, 256>>>(anchors, im_info);
    k_passB<<<NB * BPB, 256>>>(anchors, im_info, rfg, rbg);
    k_upd0<<<64, 256>>>();
    k_collect<<<(NB * TOTAL) / 256, 256>>>(rfg, rbg);
    k_finish<<<4, 256>>>();
    k_passD<<<OUTTOT / 4 / 256, 256>>>(anchors, im_info, rfg, rbg, out);
}